// round 9
// baseline (speedup 1.0000x reference)
#include <cuda_runtime.h>

// Cubic B-spline prefilter (Unser), DCT-II mirror boundaries, as a truncated
// symmetric FIR: h[k] = sqrt(3) * p^|k|, p = sqrt(3)-2, radius 8 (17 taps).
// Monolithic two-pass pipeline (R5 structure):
//   kWH: fused W+H. Each block processes one 192x32 strip of TWO adjacent
//        slices, packed as float2 (.x=slice0, .y=slice1) -> fma.rn.f32x2
//        halves the FMA issue count.
//   kD : D axis, in place (unchanged from R5).

#define NAX   192
#define KR    8
#define NT    (2*KR + 1)        // 17 taps
#define TW    32                // strip output width
#define LC    (TW + 2*KR)       // 48 loaded cols (halo +-8)
#define P1    49                // smem pitch in float2 units
#define SEGH  8                 // H-phase outputs/thread
#define WLH   (SEGH + 2*KR)     // 24
#define SEGD  24
#define WLD   (SEGD + 2*KR)     // 40
#define TPBF  192
#define TPBD  256
#define SLICE (NAX * NAX)

typedef unsigned long long u64;

// taps T[k] = sqrt(3)*p^|k-8| as compile-time floats -> FFMA-imm in SASS (rt=1)
#define DECL_TAPS const float T[NT] = { \
     4.6023585e-05f, -1.7176230e-04f,  6.4102556e-04f, -2.3923386e-03f, \
     8.9283341e-03f, -3.3320997e-02f,  1.2435565e-01f, -4.6410161e-01f, \
     1.7320508e+00f, -4.6410161e-01f,  1.2435565e-01f, -3.3320997e-02f, \
     8.9283341e-03f, -2.3923386e-03f,  6.4102556e-04f, -1.7176230e-04f, \
     4.6023585e-05f }

__device__ __forceinline__ u64 pack2(float a, float b) {
    u64 r; asm("mov.b64 %0, {%1, %2};" : "=l"(r) : "f"(a), "f"(b)); return r;
}
__device__ __forceinline__ void ffma2(u64& d, u64 a, u64 b) {
    asm("fma.rn.f32x2 %0, %1, %2, %0;" : "+l"(d) : "l"(a), "l"(b));
}
__device__ __forceinline__ void unpack2(u64 v, float& x, float& y) {
    asm("mov.b64 {%0, %1}, %2;" : "=f"(x), "=f"(y) : "l"(v));
}

__device__ __forceinline__ int mirror_idx(int i) {
    i = (i < 0) ? (-1 - i) : i;                  // half-sample left reflect
    return (i >= NAX) ? (2 * NAX - 1 - i) : i;   // half-sample right reflect
}

// ---------------------------------------------------------------------------
// Fused W+H pass: block = pair*6 + strip; processes slices {2q, 2q+1} packed
// as float2 in one 192x49 u64 smem buffer (75 KB -> 3 blocks/SM).
// ---------------------------------------------------------------------------
__global__ __launch_bounds__(TPBF, 3) void kWH(const float* __restrict__ in,
                                               float* __restrict__ out) {
    extern __shared__ u64 s[];   // [192][P1] float2-packed

    const int tid   = threadIdx.x;              // 0..191
    const int strip = blockIdx.x % (NAX / TW);  // 6 strips
    const int q     = blockIdx.x / (NAX / TW);  // slice pair
    const int base0 = (2 * q) * SLICE;
    const int base1 = base0 + SLICE;
    const int wbase = strip * TW;

    // ---- load 192 x 48 element-pairs (two coalesced LDG.32 + STS.64)
#pragma unroll
    for (int k = 0; k < (NAX * LC) / TPBF; ++k) {   // 48 iterations
        int i   = tid + TPBF * k;
        int row = i / LC;
        int c   = i - row * LC;
        int g   = row * NAX + mirror_idx(wbase - KR + c);
        s[row * P1 + c] = pack2(in[base0 + g], in[base1 + g]);
    }
    __syncthreads();

    DECL_TAPS;
    u64 T2[NT];
#pragma unroll
    for (int k = 0; k < NT; ++k) T2[k] = pack2(T[k], T[k]);

    // ---- W filter in place: thread owns row `tid` (17-deep f32x2 delay line)
    {
        u64* rp = &s[tid * P1];   // stride-49 u64 -> conflict-free
        u64 win[NT];
#pragma unroll
        for (int m = 0; m < NT - 1; ++m) win[m] = rp[m];   // preload cols 0..15
#pragma unroll
        for (int j = 0; j < TW; ++j) {
            win[NT - 1] = rp[j + 2 * KR];                  // read col j+16
            u64 acc = 0ULL;                                 // (0.0f, 0.0f)
#pragma unroll
            for (int k = 0; k < NT; ++k) ffma2(acc, T2[k], win[k]);
            rp[j + KR] = acc;                              // write col j+8
#pragma unroll
            for (int m = 0; m < NT - 1; ++m) win[m] = win[m + 1];  // reg rotate
        }
    }
    __syncthreads();

    // ---- H filter: 768 tasks = (w 0..31) x (hseg 0..23 of 8 outputs)
#pragma unroll 1
    for (int r = 0; r < 4; ++r) {
        const int t    = tid + TPBF * r;
        const int w    = t & (TW - 1);
        const int hseg = t >> 5;                 // 0..23
        const int h0   = hseg * SEGH;

        u64 win[WLH];
#pragma unroll
        for (int m = 0; m < WLH; ++m)
            win[m] = s[mirror_idx(h0 - KR + m) * P1 + KR + w];  // LDS.64 conflict-free

        float* o0 = out + base0 + wbase + w;
        float* o1 = out + base1 + wbase + w;
#pragma unroll
        for (int j = 0; j < SEGH; ++j) {
            u64 acc = 0ULL;
#pragma unroll
            for (int k = 0; k < NT; ++k) ffma2(acc, T2[k], win[j + k]);
            float fx, fy; unpack2(acc, fx, fy);
            o0[(h0 + j) * NAX] = fx;             // 128B coalesced per j
            o1[(h0 + j) * NAX] = fy;
        }
    }
}

// ---------------------------------------------------------------------------
// D pass (stride 192*192), in place. Tile: 192(d) x 32(w).  (R5, unchanged)
// ---------------------------------------------------------------------------
__global__ __launch_bounds__(TPBD, 5) void kD(float* buf) {
    __shared__ float s[NAX][32];
    const int tid = threadIdx.x;
    const int c   = blockIdx.x % (NAX / 32);
    const int tt  = blockIdx.x / (NAX / 32);
    const int b   = tt / NAX;
    const int hh  = tt % NAX;
    const int base = b * (NAX * NAX * NAX) + hh * NAX + c * 32;

    const int w  = tid & 31;
    const int a4 = tid >> 5;
#pragma unroll
    for (int k = 0; k < NAX / 8; ++k)   // 24 outstanding LDG/thread
        s[a4 + 8 * k][w] = buf[base + (a4 + 8 * k) * (NAX * NAX) + w];
    __syncthreads();

    DECL_TAPS;
    const int a0 = (tid >> 5) * SEGD;
    float win[WLD];
#pragma unroll
    for (int m = 0; m < WLD; ++m)
        win[m] = s[mirror_idx(a0 - KR + m)][w];

#pragma unroll
    for (int j = 0; j < SEGD; ++j) {
        float acc = 0.0f;
#pragma unroll
        for (int k = 0; k < NT; ++k) acc = fmaf(T[k], win[j + k], acc);
        buf[base + (a0 + j) * (NAX * NAX) + w] = acc;     // 128B coalesced per j
    }
}

extern "C" void kernel_launch(void* const* d_in, const int* in_sizes, int n_in,
                              void* d_out, int out_size) {
    const float* x = (const float*)d_in[0];
    float* y = (float*)d_out;

    const int B = 8;   // 4 batch * 2 channel
    const int smemWH = NAX * P1 * (int)sizeof(u64);   // 75264 B

    static int attr_set = 0;
    if (!attr_set) {
        cudaFuncSetAttribute(kWH, cudaFuncAttributeMaxDynamicSharedMemorySize, smemWH);
        attr_set = 1;
    }

    const int gridWH = (B * NAX / 2) * (NAX / TW);   // 4608 blocks (slice pairs)
    const int gridD  = B * NAX * (NAX / 32);         // 9216 blocks

    kWH<<<gridWH, TPBF, smemWH>>>(x, y);  // W+H fused: d_in -> d_out
    kD<<<gridD, TPBD>>>(y);               // D axis: in place
}

// round 10
// speedup vs baseline: 1.0900x; 1.0900x over previous
#include <cuda_runtime.h>

// Cubic B-spline prefilter (Unser), DCT-II mirror boundaries, as a truncated
// symmetric FIR: h[k] = sqrt(3) * p^|k|, p = sqrt(3)-2, radius 6 (13 taps).
// R5 structure (best): kWH fused W+H on 192x32 strips (in-place register
// delay-line W filter), kD strided D pass in place.
// Halo kept at +-8 so interior strips load with aligned LDG.128.

#define NAX   192
#define KR    6
#define NT    (2*KR + 1)        // 13 taps
#define HALO  8                 // load halo (>= KR, alignment-friendly)
#define TW    32                // strip output width
#define LC    (TW + 2*HALO)     // 48 loaded cols
#define P1    49                // smem pitch (odd -> conflict-free both ways)
#define SEGH  16                // H-phase outputs/thread
#define WLH   (SEGH + 2*KR)     // 28
#define SEGD  24
#define WLD   (SEGD + 2*KR)     // 36
#define TPBF  192
#define TPBD  256

// taps T[k] = sqrt(3)*p^|k-6| as compile-time floats -> FFMA-imm in SASS (rt=1)
#define DECL_TAPS const float T[NT] = { \
     6.4102556e-04f, -2.3923386e-03f,  8.9283341e-03f, -3.3320997e-02f, \
     1.2435565e-01f, -4.6410161e-01f,  1.7320508e+00f, -4.6410161e-01f, \
     1.2435565e-01f, -3.3320997e-02f,  8.9283341e-03f, -2.3923386e-03f, \
     6.4102556e-04f }

__device__ __forceinline__ int mirror_idx(int i) {
    i = (i < 0) ? (-1 - i) : i;                  // half-sample left reflect
    return (i >= NAX) ? (2 * NAX - 1 - i) : i;   // half-sample right reflect
}

// ---------------------------------------------------------------------------
// Fused W+H pass, one 192 x 32 strip per block, one 192x49 smem buffer.
// Interior strips: aligned LDG.128 loads. W filter in place (13-deep register
// delay line; reads lead writes by 6 cols). H filter -> direct coalesced STG.
// ---------------------------------------------------------------------------
__global__ __launch_bounds__(TPBF, 6) void kWH(const float* __restrict__ in,
                                               float* __restrict__ out) {
    extern __shared__ float s[];   // [192][P1]

    const int tid   = threadIdx.x;              // 0..191
    const int strip = blockIdx.x % (NAX / TW);  // 6 strips; adjacent -> L2 halo reuse
    const int slice = blockIdx.x / (NAX / TW);
    const int base  = slice * (NAX * NAX);
    const int wbase = strip * TW;

    if (strip != 0 && strip != (NAX / TW - 1)) {
        // ---- interior: 12 aligned float4 loads/thread ((wbase-8)*4 is 32B-aligned)
        const float* rowbase = in + base + (wbase - HALO);
#pragma unroll
        for (int k = 0; k < (NAX * LC / 4) / TPBF; ++k) {   // 12 iterations
            int i   = tid + TPBF * k;
            int row = i / (LC / 4);
            int qc  = i - row * (LC / 4);
            float4 v = *(const float4*)(rowbase + row * NAX + 4 * qc);
            int o = row * P1 + 4 * qc;
            s[o] = v.x; s[o + 1] = v.y; s[o + 2] = v.z; s[o + 3] = v.w;
        }
    } else {
        // ---- edge: scalar mirrored loads
#pragma unroll
        for (int k = 0; k < (NAX * LC) / TPBF; ++k) {       // 48 iterations
            int i   = tid + TPBF * k;
            int row = i / LC;
            int c   = i - row * LC;
            s[row * P1 + c] = in[base + row * NAX + mirror_idx(wbase - HALO + c)];
        }
    }
    __syncthreads();

    DECL_TAPS;

    // ---- W filter in place: thread owns row `tid`.
    // Output j needs smem cols (j+2)..(j+14); write col j+8 after reading
    // col j+14 -> later iterations touch smem only at cols >= j+15. Safe.
    {
        float* rp = &s[tid * P1];   // lanes: stride-49 -> conflict-free
        float win[NT];
#pragma unroll
        for (int m = 0; m < NT - 1; ++m) win[m] = rp[2 + m];   // cols 2..13
#pragma unroll
        for (int j = 0; j < TW; ++j) {
            win[NT - 1] = rp[j + HALO + KR];                   // col j+14
            float acc = 0.0f;
#pragma unroll
            for (int k = 0; k < NT; ++k) acc = fmaf(T[k], win[k], acc);
            rp[j + HALO] = acc;                                // col j+8
#pragma unroll
            for (int m = 0; m < NT - 1; ++m) win[m] = win[m + 1];  // reg rotate
        }
    }
    __syncthreads();

    // ---- H filter: 384 tasks = (w 0..31) x (hseg 0..11 of 16 outputs)
#pragma unroll
    for (int r = 0; r < 2; ++r) {
        const int t    = tid + TPBF * r;
        const int w    = t & (TW - 1);
        const int hseg = t >> 5;                 // 0..11
        const int h0   = hseg * SEGH;

        float win[WLH];
#pragma unroll
        for (int m = 0; m < WLH; ++m)
            win[m] = s[mirror_idx(h0 - KR + m) * P1 + HALO + w];  // lane = w -> conflict-free

        float* o = out + base + wbase + w;
#pragma unroll
        for (int j = 0; j < SEGH; ++j) {
            float acc = 0.0f;
#pragma unroll
            for (int k = 0; k < NT; ++k) acc = fmaf(T[k], win[j + k], acc);
            o[(h0 + j) * NAX] = acc;             // 128B coalesced per j
        }
    }
}

// ---------------------------------------------------------------------------
// D pass (stride 192*192), in place. Tile: 192(d) x 32(w).
// ---------------------------------------------------------------------------
__global__ __launch_bounds__(TPBD, 5) void kD(float* buf) {
    __shared__ float s[NAX][32];
    const int tid = threadIdx.x;
    const int c   = blockIdx.x % (NAX / 32);
    const int tt  = blockIdx.x / (NAX / 32);
    const int b   = tt / NAX;
    const int hh  = tt % NAX;
    const int base = b * (NAX * NAX * NAX) + hh * NAX + c * 32;

    const int w  = tid & 31;
    const int a4 = tid >> 5;
#pragma unroll
    for (int k = 0; k < NAX / 8; ++k)   // 24 outstanding LDG/thread
        s[a4 + 8 * k][w] = buf[base + (a4 + 8 * k) * (NAX * NAX) + w];
    __syncthreads();

    DECL_TAPS;
    const int a0 = (tid >> 5) * SEGD;
    float win[WLD];
#pragma unroll
    for (int m = 0; m < WLD; ++m)
        win[m] = s[mirror_idx(a0 - KR + m)][w];

#pragma unroll
    for (int j = 0; j < SEGD; ++j) {
        float acc = 0.0f;
#pragma unroll
        for (int k = 0; k < NT; ++k) acc = fmaf(T[k], win[j + k], acc);
        buf[base + (a0 + j) * (NAX * NAX) + w] = acc;     // 128B coalesced per j
    }
}

extern "C" void kernel_launch(void* const* d_in, const int* in_sizes, int n_in,
                              void* d_out, int out_size) {
    const float* x = (const float*)d_in[0];
    float* y = (float*)d_out;

    const int B = 8;   // 4 batch * 2 channel
    const int smemWH = NAX * P1 * (int)sizeof(float);   // 37632 B

    static int attr_set = 0;
    if (!attr_set) {
        cudaFuncSetAttribute(kWH, cudaFuncAttributeMaxDynamicSharedMemorySize, smemWH);
        attr_set = 1;
    }

    const int gridWH = B * NAX * (NAX / TW);   // 9216 blocks
    const int gridD  = B * NAX * (NAX / 32);   // 9216 blocks

    kWH<<<gridWH, TPBF, smemWH>>>(x, y);  // W+H fused: d_in -> d_out
    kD<<<gridD, TPBD>>>(y);               // D axis: in place
}

// round 11
// speedup vs baseline: 1.3077x; 1.1997x over previous
#include <cuda_runtime.h>

// Cubic B-spline prefilter (Unser), DCT-II mirror boundaries, as a truncated
// symmetric FIR: h[k] = sqrt(3) * p^|k|, p = sqrt(3)-2, radius 6 (13 taps).
// R5 structure exactly (the proven-best operating point: occ 5, scalar
// mirrored loads, in-place register-delay-line W filter), with the KR=6
// tap set validated in R10. kD as in R10.

#define NAX   192
#define KR    6
#define NT    (2*KR + 1)        // 13 taps
#define HALO  8                 // load halo (>= KR; keeps R5 tile geometry)
#define TW    32                // strip output width
#define LC    (TW + 2*HALO)     // 48 loaded cols
#define P1    49                // smem pitch (odd -> conflict-free both ways)
#define SEGH  16                // H-phase outputs/thread
#define WLH   (SEGH + 2*KR)     // 28
#define SEGD  24
#define WLD   (SEGD + 2*KR)     // 36
#define TPBF  192
#define TPBD  256

// taps T[k] = sqrt(3)*p^|k-6| as compile-time floats -> FFMA-imm in SASS (rt=1)
#define DECL_TAPS const float T[NT] = { \
     6.4102556e-04f, -2.3923386e-03f,  8.9283341e-03f, -3.3320997e-02f, \
     1.2435565e-01f, -4.6410161e-01f,  1.7320508e+00f, -4.6410161e-01f, \
     1.2435565e-01f, -3.3320997e-02f,  8.9283341e-03f, -2.3923386e-03f, \
     6.4102556e-04f }

__device__ __forceinline__ int mirror_idx(int i) {
    i = (i < 0) ? (-1 - i) : i;                  // half-sample left reflect
    return (i >= NAX) ? (2 * NAX - 1 - i) : i;   // half-sample right reflect
}

// ---------------------------------------------------------------------------
// Fused W+H pass, one 192 x 32 strip per block, one 192x49 smem buffer.
// Phase 1: load 192x48 (w-halo mirrored), 48 independent coalesced LDG.
// Phase 2: W filter in place (thread = row, 13-deep register delay line).
// Phase 3: H filter on cols [8,40), direct coalesced STG.
// ---------------------------------------------------------------------------
__global__ __launch_bounds__(TPBF, 5) void kWH(const float* __restrict__ in,
                                               float* __restrict__ out) {
    extern __shared__ float s[];   // [192][P1]

    const int tid   = threadIdx.x;              // 0..191
    const int strip = blockIdx.x % (NAX / TW);  // 6 strips; adjacent -> L2 halo reuse
    const int slice = blockIdx.x / (NAX / TW);
    const int base  = slice * (NAX * NAX);
    const int wbase = strip * TW;

    // ---- load 192 x 48 (coalesced LDG, independent -> high MLP)
#pragma unroll
    for (int k = 0; k < (NAX * LC) / TPBF; ++k) {   // 48 iterations
        int i   = tid + TPBF * k;
        int row = i / LC;
        int c   = i - row * LC;
        s[row * P1 + c] = in[base + row * NAX + mirror_idx(wbase - HALO + c)];
    }
    __syncthreads();

    DECL_TAPS;

    // ---- W filter in place: thread owns row `tid`.
    // Output j needs smem cols (j+2)..(j+14); write col j+8 after reading
    // col j+14 -> later iterations read smem only at cols >= j+15. Safe.
    {
        float* rp = &s[tid * P1];   // lanes: stride-49 -> conflict-free
        float win[NT];
#pragma unroll
        for (int m = 0; m < NT - 1; ++m) win[m] = rp[2 + m];   // cols 2..13
#pragma unroll
        for (int j = 0; j < TW; ++j) {
            win[NT - 1] = rp[j + HALO + KR];                   // col j+14
            float acc = 0.0f;
#pragma unroll
            for (int k = 0; k < NT; ++k) acc = fmaf(T[k], win[k], acc);
            rp[j + HALO] = acc;                                // col j+8
#pragma unroll
            for (int m = 0; m < NT - 1; ++m) win[m] = win[m + 1];  // reg rotate
        }
    }
    __syncthreads();

    // ---- H filter: 384 tasks = (w 0..31) x (hseg 0..11 of 16 outputs)
#pragma unroll
    for (int r = 0; r < 2; ++r) {
        const int t    = tid + TPBF * r;
        const int w    = t & (TW - 1);
        const int hseg = t >> 5;                 // 0..11
        const int h0   = hseg * SEGH;

        float win[WLH];
#pragma unroll
        for (int m = 0; m < WLH; ++m)
            win[m] = s[mirror_idx(h0 - KR + m) * P1 + HALO + w];  // lane = w -> conflict-free

        float* o = out + base + wbase + w;
#pragma unroll
        for (int j = 0; j < SEGH; ++j) {
            float acc = 0.0f;
#pragma unroll
            for (int k = 0; k < NT; ++k) acc = fmaf(T[k], win[j + k], acc);
            o[(h0 + j) * NAX] = acc;             // 128B coalesced per j
        }
    }
}

// ---------------------------------------------------------------------------
// D pass (stride 192*192), in place. Tile: 192(d) x 32(w).  (R10, unchanged)
// ---------------------------------------------------------------------------
__global__ __launch_bounds__(TPBD, 5) void kD(float* buf) {
    __shared__ float s[NAX][32];
    const int tid = threadIdx.x;
    const int c   = blockIdx.x % (NAX / 32);
    const int tt  = blockIdx.x / (NAX / 32);
    const int b   = tt / NAX;
    const int hh  = tt % NAX;
    const int base = b * (NAX * NAX * NAX) + hh * NAX + c * 32;

    const int w  = tid & 31;
    const int a4 = tid >> 5;
#pragma unroll
    for (int k = 0; k < NAX / 8; ++k)   // 24 outstanding LDG/thread
        s[a4 + 8 * k][w] = buf[base + (a4 + 8 * k) * (NAX * NAX) + w];
    __syncthreads();

    DECL_TAPS;
    const int a0 = (tid >> 5) * SEGD;
    float win[WLD];
#pragma unroll
    for (int m = 0; m < WLD; ++m)
        win[m] = s[mirror_idx(a0 - KR + m)][w];

#pragma unroll
    for (int j = 0; j < SEGD; ++j) {
        float acc = 0.0f;
#pragma unroll
        for (int k = 0; k < NT; ++k) acc = fmaf(T[k], win[j + k], acc);
        buf[base + (a0 + j) * (NAX * NAX) + w] = acc;     // 128B coalesced per j
    }
}

extern "C" void kernel_launch(void* const* d_in, const int* in_sizes, int n_in,
                              void* d_out, int out_size) {
    const float* x = (const float*)d_in[0];
    float* y = (float*)d_out;

    const int B = 8;   // 4 batch * 2 channel
    const int smemWH = NAX * P1 * (int)sizeof(float);   // 37632 B

    static int attr_set = 0;
    if (!attr_set) {
        cudaFuncSetAttribute(kWH, cudaFuncAttributeMaxDynamicSharedMemorySize, smemWH);
        attr_set = 1;
    }

    const int gridWH = B * NAX * (NAX / TW);   // 9216 blocks
    const int gridD  = B * NAX * (NAX / 32);   // 9216 blocks

    kWH<<<gridWH, TPBF, smemWH>>>(x, y);  // W+H fused: d_in -> d_out
    kD<<<gridD, TPBD>>>(y);               // D axis: in place
}